// round 16
// baseline (speedup 1.0000x reference)
#include <cuda_runtime.h>

#define Nn 80
#define Fh 64
#define Hh 256
#define Zz 128
#define OFFS 3160
#define Eg 800
#define ITERS 50
#define NB 80
#define NT 320
#define BP 84

// ---------------- device scratch (static, allocation-free) ----------------
__device__ float g_U[Nn*Hh];
__device__ float g_T2[Nn*Hh];
__device__ float g_U2[Nn*Hh];
__device__ float g_he[Hh];
__device__ float g_B[Nn*Nn];
__device__ __align__(16) float g_M[2][Nn*Nn];  // double-buffered M exchange
__device__ float g_flag[ITERS][NB];            // per-iter per-CTA X-max (nonzero = published)
__device__ float g_sf[4][NB];                  // stage flags: 0=U, 1=T2, 2=U2, 3=B
__device__ float g_hf[1];                      // he ready
__device__ float g_nrm[NB];

// ---------------- sync primitives ----------------
__device__ __forceinline__ float ld_acq_f(const float* p) {
    float v;
    asm volatile("ld.acquire.gpu.global.f32 %0, [%1];" : "=f"(v) : "l"(p) : "memory");
    return v;
}
__device__ __forceinline__ void st_rel_f(float* p, float v) {
    asm volatile("st.release.gpu.global.f32 [%0], %1;" :: "l"(p), "f"(v) : "memory");
}
__device__ __forceinline__ void ld_cg_v4(const float* p, float4& v) {
    asm volatile("ld.global.cg.v4.f32 {%0,%1,%2,%3}, [%4];"
                 : "=f"(v.x), "=f"(v.y), "=f"(v.z), "=f"(v.w) : "l"(p) : "memory");
}

// ============ launch 1: reset cross-CTA state (replay-safe) ===============
__global__ void k_init() {
    int i = blockIdx.x * blockDim.x + threadIdx.x;
    int nstep = gridDim.x * blockDim.x;
    for (int k = i; k < ITERS*NB; k += nstep) ((float*)g_flag)[k] = 0.f;
    for (int k = i; k < 4*NB; k += nstep) ((float*)g_sf)[k] = 0.f;
    for (int k = i; k < NB; k += nstep) g_nrm[k] = 0.f;
    if (i == 0) g_hf[0] = 0.f;
}

// ============ launch 2: everything (persistent, 80 CTAs, 1 X-row each) ====
__global__ void __launch_bounds__(NT, 1) k_main(
    const float* __restrict__ x,   const int* __restrict__ ei,
    const int* __restrict__ adj,   const float* __restrict__ eps,
    const float* __restrict__ W1,  const float* __restrict__ b1,
    const float* __restrict__ g1,  const float* __restrict__ bt1,
    const float* __restrict__ W2,  const float* __restrict__ b2,
    const float* __restrict__ g2,  const float* __restrict__ bt2,
    const float* __restrict__ Wmu, const float* __restrict__ bmu,
    const float* __restrict__ Wlv, const float* __restrict__ blv,
    const float* __restrict__ We1, const float* __restrict__ be1,
    const float* __restrict__ We2, const float* __restrict__ be2,
    float* __restrict__ out)
{
    __shared__ int   se[2*Eg];
    __shared__ int   cnt[Nn];
    __shared__ int   acnt[Nn];
    __shared__ float dinv[Nn];
    __shared__ float Ag_s[Nn];
    __shared__ __align__(16) float As[BP];     // own A' row
    __shared__ __align__(16) float Xs[BP];     // own X row (local all iterations)
    __shared__ float nss[BP];                  // own node_sim row
    __shared__ float dBs[BP];
    __shared__ float Bs[Nn*BP];                // full B'
    __shared__ float y64[Fh];
    __shared__ float Hrow[Hh];
    __shared__ float he_s[Hh];
    __shared__ float gv[Hh];
    __shared__ float zv[Zz];
    __shared__ __align__(16) float p1[Nn*4];
    __shared__ float red[NT/32];
    __shared__ float sgv[4];
    const int t = threadIdx.x, c = blockIdx.x;

    // ---------------- S0: degrees, Ag row c, A' row c ----------------
    for (int e = t; e < 2*Eg; e += NT) se[e] = ei[e];
    if (t < Nn) { cnt[t] = 1; acnt[t] = 0; }
    __syncthreads();
    for (int e = t; e < Eg; e += NT) atomicAdd(&cnt[se[Eg+e]], 1);
    for (int e = t; e < Eg; e += NT)
        if (se[Eg+e] == c) atomicAdd(&acnt[se[e]], 1);
    __syncthreads();
    if (t < Nn) dinv[t] = rsqrtf((float)cnt[t]);
    __syncthreads();
    if (t < Nn) {
        float v = (float)acnt[t] * dinv[t] * dinv[c];
        if (t == c) v += dinv[c] * dinv[c];
        Ag_s[t] = v;
        As[t] = (t != c && ((adj[c*Nn+t] | adj[t*Nn+c]) != 0)) ? 1.f : 0.f;
    }
    __syncthreads();

    // ---------------- S1: U row c = (Ag_c . x) W1 + b1 ----------------
    if (t < Fh) {
        float yv = 0.f;
        #pragma unroll 16
        for (int j = 0; j < Nn; ++j) yv += Ag_s[j] * __ldg(&x[j*Fh + t]);
        y64[t] = yv;
    }
    __syncthreads();
    if (t < Hh) {
        float u = b1[t];
        #pragma unroll 16
        for (int k = 0; k < Fh; ++k) u += y64[k] * __ldg(&W1[k*Hh + t]);
        g_U[c*Hh + t] = u;
    }
    __syncthreads();
    if (t == 0) st_rel_f(&g_sf[0][c], 1.f);

    // ---------------- S2: BN1 + ReLU (own row) -> T2 = Hrow @ W2 ------
    if (t < Nn) { while (ld_acq_f(&g_sf[0][t]) == 0.f) { } }
    __syncthreads();
    if (t < Hh) {
        float s = 0.f, s2 = 0.f, urow = 0.f;
        #pragma unroll 16
        for (int i = 0; i < Nn; ++i) {
            float u = __ldcg(&g_U[i*Hh + t]);
            s += u; s2 += u*u;
            if (i == c) urow = u;
        }
        float m = s * (1.f/Nn);
        float v = s2 * (1.f/Nn) - m*m;
        float sc = g1[t] * rsqrtf(fmaxf(v, 0.f) + 1e-5f);
        Hrow[t] = fmaxf((urow - m)*sc + bt1[t], 0.f);
    }
    __syncthreads();
    if (t < Hh) {
        float acc = 0.f;
        #pragma unroll 16
        for (int k = 0; k < Hh; ++k) acc += Hrow[k] * __ldg(&W2[k*Hh + t]);
        g_T2[c*Hh + t] = acc;
    }
    __syncthreads();
    if (t == 0) st_rel_f(&g_sf[1][c], 1.f);

    // ---------------- S3: U2 row c = Ag_c @ T2 + b2 ----------------
    if (t < Nn) { while (ld_acq_f(&g_sf[1][t]) == 0.f) { } }
    __syncthreads();
    if (t < Hh) {
        float u = b2[t];
        #pragma unroll 16
        for (int j = 0; j < Nn; ++j) u += Ag_s[j] * __ldcg(&g_T2[j*Hh + t]);
        g_U2[c*Hh + t] = u;
    }
    __syncthreads();
    if (t == 0) st_rel_f(&g_sf[2][c], 1.f);

    // ---------------- S4: head (CTA 0 only) ----------------
    if (c == 0) {
        if (t < Nn) { while (ld_acq_f(&g_sf[2][t]) == 0.f) { } }
        __syncthreads();
        if (t < Hh) {
            float s = 0.f, s2 = 0.f;
            #pragma unroll 16
            for (int i = 0; i < Nn; ++i) { float u = __ldcg(&g_U2[i*Hh + t]); s += u; s2 += u*u; }
            float m = s * (1.f/Nn);
            float v = s2 * (1.f/Nn) - m*m;
            float sc = g2[t] * rsqrtf(fmaxf(v, 0.f) + 1e-5f), bo = bt2[t];
            float gs = 0.f;
            #pragma unroll 16
            for (int i = 0; i < Nn; ++i) {
                float u = __ldcg(&g_U2[i*Hh + t]);
                gs += fmaxf((u - m)*sc + bo, 0.f);
            }
            gv[t] = gs * (1.f/Nn);
        }
        __syncthreads();
        if (t < Zz) {
            float mu = bmu[t], lv = blv[t];
            #pragma unroll 16
            for (int f = 0; f < Hh; ++f) { mu += gv[f]*__ldg(&Wmu[f*Zz + t]); lv += gv[f]*__ldg(&Wlv[f*Zz + t]); }
            lv = fminf(fmaxf(lv, -4.f), 4.f);
            zv[t] = mu + eps[t] * expf(0.5f * lv);
        }
        __syncthreads();
        if (t < Hh) {
            float h = be1[t];
            #pragma unroll 16
            for (int z = 0; z < Zz; ++z) h += zv[z] * __ldg(&We1[z*Hh + t]);
            g_he[t] = fmaxf(h, 0.f);
        }
        __syncthreads();
        if (t == 0) st_rel_f(&g_hf[0], 1.f);
    }
    if (t == 0) { while (ld_acq_f(&g_hf[0]) == 0.f) { } }
    __syncthreads();
    if (t < Hh) he_s[t] = __ldcg(&g_he[t]);
    __syncthreads();

    // ---------------- S5: decoder (40 outputs/CTA, 4-way split) -------
    if (t < 160) {
        int ol = t >> 2, q = t & 3;
        int o = c*40 + ol;
        float acc = 0.f;
        if (o < OFFS) {
            #pragma unroll 16
            for (int hh = q*64; hh < q*64 + 64; ++hh) acc += he_s[hh] * __ldg(&We2[hh*OFFS + o]);
        }
        p1[ol*4 + q] = acc;
    }
    __syncthreads();
    if (t < 40) {
        int o = c*40 + t;
        if (o < OFFS) {
            float4 pv = *(float4*)&p1[t*4];
            float acc = pv.x + pv.y + pv.z + pv.w + be2[o];
            float sgm = 1.f / (1.f + expf(-acc));
            int i = 0, rem = o;
            while (rem >= (Nn-1) - i) { rem -= (Nn-1) - i; ++i; }
            int j = i + 1 + rem;
            g_B[i*Nn + j] = sgm;
            g_B[j*Nn + i] = sgm;
        }
    }
    __syncthreads();
    if (t == 0) st_rel_f(&g_sf[3][c], 1.f);
    if (t < Nn) { while (ld_acq_f(&g_sf[3][t]) == 0.f) { } }
    __syncthreads();

    // ---- full B' into SMEM (diag masked 0), degrees, node_sim, X0 ----
    for (int idx = t; idx < Nn*Nn; idx += NT) {
        int r = idx / Nn, cc = idx - r*Nn;
        Bs[r*BP + cc] = (r == cc) ? 0.f : __ldcg(&g_B[idx]);
    }
    __syncthreads();
    if (t == 0) {
        float s = 1.f;
        #pragma unroll 10
        for (int j = 0; j < Nn; ++j) s += As[j];
        sgv[1] = s;
        red[0] = 1.f; red[1] = 0.f; red[2] = 0.f;   // X^0 max = 1
    }
    __syncthreads();
    if (t < Nn) {
        float s = 1.f;
        #pragma unroll 10
        for (int j = 0; j < Nn; ++j) s += Bs[t*BP + j];
        dBs[t] = s;
        nss[t] = 1.f / (fabsf(sgv[1] - s) + 1.f);
        Xs[t] = 1.f;
    }
    __syncthreads();

    // ---------------- MPM: 50 iterations, flag-synced M exchange ------
    const int a = t % Nn;     // M row
    const int h = t / Nn;     // quarter (b/j range 20h..20h+19)

    for (int it = 0; it < ITERS; ++it) {
        float* Mb = g_M[it & 1];

        // ---- step 1 partial: max over b-quarter of B[a][b]*X[b] ----
        {
            const float4* Bq = (const float4*)&Bs[a*BP + 20*h];
            const float4* Xq = (const float4*)&Xs[20*h];
            float m = 0.f;
            #pragma unroll
            for (int k = 0; k < 5; ++k) {
                float4 b4 = Bq[k], x4 = Xq[k];
                m = fmaxf(m, b4.x*x4.x); m = fmaxf(m, b4.y*x4.y);
                m = fmaxf(m, b4.z*x4.z); m = fmaxf(m, b4.w*x4.w);
            }
            p1[a*4 + h] = m;
        }
        __syncthreads();
        if (t < Nn) {
            float4 pv = *(float4*)&p1[t*4];
            Mb[t*Nn + c] = fmaxf(fmaxf(pv.x, pv.y), fmaxf(pv.z, pv.w));
        }
        __syncthreads();

        // ---- publish flag (value = local X^it max), poll all 80 ----
        if (t == 0) {
            float lm = fmaxf(red[0], fmaxf(red[1], red[2]));
            st_rel_f(&g_flag[it][c], lm);
        }
        if (t < 32) {
            const float* fl = g_flag[it];
            float v0, v1, v2;
            bool ok;
            do {
                v0 = ld_acq_f(&fl[t]);
                v1 = ld_acq_f(&fl[t + 32]);
                v2 = (t < 16) ? ld_acq_f(&fl[t + 64]) : 1.f;
                ok = (v0 != 0.f) && (v1 != 0.f) && (v2 != 0.f);
            } while (__ballot_sync(0xffffffffu, ok) != 0xffffffffu);
            float gm = fmaxf(v0, v1);
            if (t < 16) gm = fmaxf(gm, v2);
            #pragma unroll
            for (int o2 = 16; o2; o2 >>= 1) gm = fmaxf(gm, __shfl_xor_sync(0xffffffffu, gm, o2));
            if (t == 0) {
                unsigned mb = __float_as_uint(gm);
                sgv[0] = __uint_as_float((254u - ((mb >> 23) & 255u)) << 23);
            }
        }
        __syncthreads();

        // ---- step 2 partial: sum over j-quarter of A[j]*M[a][j] ----
        {
            const float* base = &Mb[a*Nn + 20*h];
            float4 v0, v1, v2, v3, v4;
            ld_cg_v4(base,      v0);
            ld_cg_v4(base + 4,  v1);
            ld_cg_v4(base + 8,  v2);
            ld_cg_v4(base + 12, v3);
            ld_cg_v4(base + 16, v4);
            const float4* Aq = (const float4*)&As[20*h];
            float4 a0 = Aq[0], a1 = Aq[1], a2 = Aq[2], a3 = Aq[3], a4 = Aq[4];
            float s0 = a0.x*v0.x + a0.y*v0.y + a0.z*v0.z + a0.w*v0.w;
            float s1 = a1.x*v1.x + a1.y*v1.y + a1.z*v1.z + a1.w*v1.w;
            float s2 = a2.x*v2.x + a2.y*v2.y + a2.z*v2.z + a2.w*v2.w;
            float s3 = a3.x*v3.x + a3.y*v3.y + a3.z*v3.z + a3.w*v3.w;
            float s4 = a4.x*v4.x + a4.y*v4.y + a4.z*v4.z + a4.w*v4.w;
            p1[a*4 + h] = (s0 + s1) + (s2 + s3) + s4;
        }
        __syncthreads();

        // ---- combine, scale, update local X ----
        float lmax = 0.f;
        if (t < Nn) {
            float4 pv = *(float4*)&p1[t*4];
            float xn = sgv[0] * ((pv.x + pv.y + pv.z + pv.w) + nss[t] * Xs[t]);
            Xs[t] = xn;
            lmax = xn;
        }
        #pragma unroll
        for (int o2 = 16; o2; o2 >>= 1) lmax = fmaxf(lmax, __shfl_xor_sync(0xffffffffu, lmax, o2));
        if ((t & 31) == 0 && t < 96) red[t >> 5] = lmax;
        __syncthreads();
    }

    // ---------------- final global L2 norm (deterministic) -----------
    if (t < Nn) p1[t] = Xs[t] * Xs[t];
    __syncthreads();
    if (t == 0) {
        float ss2 = 0.f;
        #pragma unroll 16
        for (int k = 0; k < Nn; ++k) ss2 += p1[k];
        st_rel_f(&g_nrm[c], ss2);
    }
    if (t < 32) {
        bool ok;
        do {
            float v0 = ld_acq_f(&g_nrm[t]);
            float v1 = ld_acq_f(&g_nrm[t + 32]);
            float v2 = (t < 16) ? ld_acq_f(&g_nrm[t + 64]) : 1.f;
            ok = (v0 != 0.f) && (v1 != 0.f) && (v2 != 0.f);
        } while (__ballot_sync(0xffffffffu, ok) != 0xffffffffu);
    }
    __syncthreads();
    if (t == 0) {
        float tot = 0.f;
        #pragma unroll 16
        for (int k = 0; k < Nn; ++k) tot += __ldcg(&g_nrm[k]);   // fixed order everywhere
        sgv[0] = 1.f / sqrtf(tot);
    }
    __syncthreads();
    if (t < Nn) out[c*Nn + t] = Xs[t] * sgv[0];
}

// ---------------- launch ----------------
extern "C" void kernel_launch(void* const* d_in, const int* in_sizes, int n_in,
                              void* d_out, int out_size) {
    const float* x   = (const float*)d_in[0];
    const int*   ei  = (const int*)  d_in[1];
    const int*   adj = (const int*)  d_in[2];
    const float* eps = (const float*)d_in[3];
    const float* W1  = (const float*)d_in[4];
    const float* b1  = (const float*)d_in[5];
    const float* g1  = (const float*)d_in[6];
    const float* bt1 = (const float*)d_in[7];
    const float* W2  = (const float*)d_in[8];
    const float* b2  = (const float*)d_in[9];
    const float* g2  = (const float*)d_in[10];
    const float* bt2 = (const float*)d_in[11];
    const float* Wmu = (const float*)d_in[12];
    const float* bmu = (const float*)d_in[13];
    const float* Wlv = (const float*)d_in[14];
    const float* blv = (const float*)d_in[15];
    const float* We1 = (const float*)d_in[16];
    const float* be1 = (const float*)d_in[17];
    const float* We2 = (const float*)d_in[18];
    const float* be2 = (const float*)d_in[19];
    // d_in[20..23] (Wn*, bn*) are dead: B's diagonal is overwritten with 1.

    k_init<<<16, 256>>>();
    k_main<<<NB, NT>>>(x, ei, adj, eps, W1, b1, g1, bt1, W2, b2, g2, bt2,
                       Wmu, bmu, Wlv, blv, We1, be1, We2, be2, (float*)d_out);
}

// round 17
// speedup vs baseline: 1.6514x; 1.6514x over previous
#include <cuda_runtime.h>

#define Nn 80
#define Fh 64
#define Hh 256
#define Zz 128
#define OFFS 3160
#define Eg 800
#define ITERS 50
#define NB 80
#define NT 320
#define BP 84

// ---------------- device scratch (static, allocation-free) ----------------
__device__ float g_U[Nn*Hh];
__device__ float g_T2[Nn*Hh];
__device__ float g_U2[Nn*Hh];
__device__ float g_he[Hh];
__device__ float g_B[Nn*Nn];
__device__ __align__(16) float g_M[2][Nn*Nn];  // double-buffered M exchange
__device__ unsigned g_cnt[ITERS];              // per-iteration arrival counters
__device__ float g_sf[4][NB];                  // stage flags: 0=U, 1=T2, 2=U2, 3=B
__device__ float g_hf[1];                      // he ready
__device__ float g_nrm[NB];

// ---------------- sync primitives ----------------
__device__ __forceinline__ float ld_acq_f(const float* p) {
    float v;
    asm volatile("ld.acquire.gpu.global.f32 %0, [%1];" : "=f"(v) : "l"(p) : "memory");
    return v;
}
__device__ __forceinline__ void st_rel_f(float* p, float v) {
    asm volatile("st.release.gpu.global.f32 [%0], %1;" :: "l"(p), "f"(v) : "memory");
}
__device__ __forceinline__ void red_rel_add_u32(unsigned* p, unsigned v) {
    asm volatile("red.release.gpu.global.add.u32 [%0], %1;" :: "l"(p), "r"(v) : "memory");
}
__device__ __forceinline__ unsigned ld_acq_u32(const unsigned* p) {
    unsigned v;
    asm volatile("ld.acquire.gpu.global.u32 %0, [%1];" : "=r"(v) : "l"(p) : "memory");
    return v;
}
__device__ __forceinline__ void ld_cg_v4(const float* p, float4& v) {
    asm volatile("ld.global.cg.v4.f32 {%0,%1,%2,%3}, [%4];"
                 : "=f"(v.x), "=f"(v.y), "=f"(v.z), "=f"(v.w) : "l"(p) : "memory");
}

// ============ launch 1: reset cross-CTA state (replay-safe) ===============
__global__ void k_init() {
    int i = blockIdx.x * blockDim.x + threadIdx.x;
    int nstep = gridDim.x * blockDim.x;
    for (int k = i; k < ITERS; k += nstep) g_cnt[k] = 0u;
    for (int k = i; k < 4*NB; k += nstep) ((float*)g_sf)[k] = 0.f;
    for (int k = i; k < NB; k += nstep) g_nrm[k] = 0.f;
    if (i == 0) g_hf[0] = 0.f;
}

// ============ launch 2: everything (persistent, 80 CTAs, 1 X-row each) ====
__global__ void __launch_bounds__(NT, 1) k_main(
    const float* __restrict__ x,   const int* __restrict__ ei,
    const int* __restrict__ adj,   const float* __restrict__ eps,
    const float* __restrict__ W1,  const float* __restrict__ b1,
    const float* __restrict__ g1,  const float* __restrict__ bt1,
    const float* __restrict__ W2,  const float* __restrict__ b2,
    const float* __restrict__ g2,  const float* __restrict__ bt2,
    const float* __restrict__ Wmu, const float* __restrict__ bmu,
    const float* __restrict__ Wlv, const float* __restrict__ blv,
    const float* __restrict__ We1, const float* __restrict__ be1,
    const float* __restrict__ We2, const float* __restrict__ be2,
    float* __restrict__ out)
{
    __shared__ int   se[2*Eg];
    __shared__ int   cnt[Nn];
    __shared__ int   acnt[Nn];
    __shared__ float dinv[Nn];
    __shared__ float Ag_s[Nn];
    __shared__ __align__(16) float As[BP];     // own A' row
    __shared__ __align__(16) float Xs[BP];     // own X row (local all iterations)
    __shared__ float nss[BP];                  // own node_sim row
    __shared__ float dBs[BP];
    __shared__ float Bs[Nn*BP];                // full B'
    __shared__ float y64[Fh];
    __shared__ float Hrow[Hh];
    __shared__ float he_s[Hh];
    __shared__ float gv[Hh];
    __shared__ float zv[Zz];
    __shared__ __align__(16) float p1[Nn*4];
    __shared__ float wmax[NT/32];
    __shared__ float sgv[4];
    const int t = threadIdx.x, c = blockIdx.x;

    // ---------------- S0: degrees, Ag row c, A' row c ----------------
    for (int e = t; e < 2*Eg; e += NT) se[e] = ei[e];
    if (t < Nn) { cnt[t] = 1; acnt[t] = 0; }
    __syncthreads();
    for (int e = t; e < Eg; e += NT) atomicAdd(&cnt[se[Eg+e]], 1);
    for (int e = t; e < Eg; e += NT)
        if (se[Eg+e] == c) atomicAdd(&acnt[se[e]], 1);
    __syncthreads();
    if (t < Nn) dinv[t] = rsqrtf((float)cnt[t]);
    __syncthreads();
    if (t < Nn) {
        float v = (float)acnt[t] * dinv[t] * dinv[c];
        if (t == c) v += dinv[c] * dinv[c];
        Ag_s[t] = v;
        As[t] = (t != c && ((adj[c*Nn+t] | adj[t*Nn+c]) != 0)) ? 1.f : 0.f;
    }
    __syncthreads();

    // ---------------- S1: U row c = (Ag_c . x) W1 + b1 ----------------
    if (t < Fh) {
        float yv = 0.f;
        #pragma unroll 16
        for (int j = 0; j < Nn; ++j) yv += Ag_s[j] * __ldg(&x[j*Fh + t]);
        y64[t] = yv;
    }
    __syncthreads();
    if (t < Hh) {
        float u = b1[t];
        #pragma unroll 16
        for (int k = 0; k < Fh; ++k) u += y64[k] * __ldg(&W1[k*Hh + t]);
        g_U[c*Hh + t] = u;
    }
    __syncthreads();
    if (t == 0) st_rel_f(&g_sf[0][c], 1.f);

    // ---------------- S2: BN1 + ReLU (own row) -> T2 = Hrow @ W2 ------
    if (t < Nn) { while (ld_acq_f(&g_sf[0][t]) == 0.f) { } }
    __syncthreads();
    if (t < Hh) {
        float s = 0.f, s2 = 0.f, urow = 0.f;
        #pragma unroll 16
        for (int i = 0; i < Nn; ++i) {
            float u = __ldcg(&g_U[i*Hh + t]);
            s += u; s2 += u*u;
            if (i == c) urow = u;
        }
        float m = s * (1.f/Nn);
        float v = s2 * (1.f/Nn) - m*m;
        float sc = g1[t] * rsqrtf(fmaxf(v, 0.f) + 1e-5f);
        Hrow[t] = fmaxf((urow - m)*sc + bt1[t], 0.f);
    }
    __syncthreads();
    if (t < Hh) {
        float acc = 0.f;
        #pragma unroll 16
        for (int k = 0; k < Hh; ++k) acc += Hrow[k] * __ldg(&W2[k*Hh + t]);
        g_T2[c*Hh + t] = acc;
    }
    __syncthreads();
    if (t == 0) st_rel_f(&g_sf[1][c], 1.f);

    // ---------------- S3: U2 row c = Ag_c @ T2 + b2 ----------------
    if (t < Nn) { while (ld_acq_f(&g_sf[1][t]) == 0.f) { } }
    __syncthreads();
    if (t < Hh) {
        float u = b2[t];
        #pragma unroll 16
        for (int j = 0; j < Nn; ++j) u += Ag_s[j] * __ldcg(&g_T2[j*Hh + t]);
        g_U2[c*Hh + t] = u;
    }
    __syncthreads();
    if (t == 0) st_rel_f(&g_sf[2][c], 1.f);

    // ---------------- S4: head (CTA 0 only) ----------------
    if (c == 0) {
        if (t < Nn) { while (ld_acq_f(&g_sf[2][t]) == 0.f) { } }
        __syncthreads();
        if (t < Hh) {
            float s = 0.f, s2 = 0.f;
            #pragma unroll 16
            for (int i = 0; i < Nn; ++i) { float u = __ldcg(&g_U2[i*Hh + t]); s += u; s2 += u*u; }
            float m = s * (1.f/Nn);
            float v = s2 * (1.f/Nn) - m*m;
            float sc = g2[t] * rsqrtf(fmaxf(v, 0.f) + 1e-5f), bo = bt2[t];
            float gs = 0.f;
            #pragma unroll 16
            for (int i = 0; i < Nn; ++i) {
                float u = __ldcg(&g_U2[i*Hh + t]);
                gs += fmaxf((u - m)*sc + bo, 0.f);
            }
            gv[t] = gs * (1.f/Nn);
        }
        __syncthreads();
        if (t < Zz) {
            float mu = bmu[t], lv = blv[t];
            #pragma unroll 16
            for (int f = 0; f < Hh; ++f) { mu += gv[f]*__ldg(&Wmu[f*Zz + t]); lv += gv[f]*__ldg(&Wlv[f*Zz + t]); }
            lv = fminf(fmaxf(lv, -4.f), 4.f);
            zv[t] = mu + eps[t] * expf(0.5f * lv);
        }
        __syncthreads();
        if (t < Hh) {
            float h = be1[t];
            #pragma unroll 16
            for (int z = 0; z < Zz; ++z) h += zv[z] * __ldg(&We1[z*Hh + t]);
            g_he[t] = fmaxf(h, 0.f);
        }
        __syncthreads();
        if (t == 0) st_rel_f(&g_hf[0], 1.f);
    }
    if (t == 0) { while (ld_acq_f(&g_hf[0]) == 0.f) { } }
    __syncthreads();
    if (t < Hh) he_s[t] = __ldcg(&g_he[t]);
    __syncthreads();

    // ---------------- S5: decoder (40 outputs/CTA, 4-way split) -------
    if (t < 160) {
        int ol = t >> 2, q = t & 3;
        int o = c*40 + ol;
        float acc = 0.f;
        if (o < OFFS) {
            #pragma unroll 16
            for (int hh = q*64; hh < q*64 + 64; ++hh) acc += he_s[hh] * __ldg(&We2[hh*OFFS + o]);
        }
        p1[ol*4 + q] = acc;
    }
    __syncthreads();
    if (t < 40) {
        int o = c*40 + t;
        if (o < OFFS) {
            float4 pv = *(float4*)&p1[t*4];
            float acc = pv.x + pv.y + pv.z + pv.w + be2[o];
            float sgm = 1.f / (1.f + expf(-acc));
            int i = 0, rem = o;
            while (rem >= (Nn-1) - i) { rem -= (Nn-1) - i; ++i; }
            int j = i + 1 + rem;
            g_B[i*Nn + j] = sgm;
            g_B[j*Nn + i] = sgm;
        }
    }
    __syncthreads();
    if (t == 0) st_rel_f(&g_sf[3][c], 1.f);
    if (t < Nn) { while (ld_acq_f(&g_sf[3][t]) == 0.f) { } }
    __syncthreads();

    // ---- full B' into SMEM (diag masked 0), degrees, node_sim, X0 ----
    for (int idx = t; idx < Nn*Nn; idx += NT) {
        int r = idx / Nn, cc = idx - r*Nn;
        Bs[r*BP + cc] = (r == cc) ? 0.f : __ldcg(&g_B[idx]);
    }
    __syncthreads();
    if (t == 0) {
        float s = 1.f;
        #pragma unroll 10
        for (int j = 0; j < Nn; ++j) s += As[j];
        sgv[1] = s;
    }
    __syncthreads();
    if (t < Nn) {
        float s = 1.f;
        #pragma unroll 10
        for (int j = 0; j < Nn; ++j) s += Bs[t*BP + j];
        dBs[t] = s;
        nss[t] = 1.f / (fabsf(sgv[1] - s) + 1.f);
        Xs[t] = 1.f;
    }
    __syncthreads();

    // ---------------- MPM: 50 iterations, counter-synced M exchange ---
    const int a = t % Nn;     // M row
    const int h = t / Nn;     // quarter (b/j range 20h..20h+19)

    for (int it = 0; it < ITERS; ++it) {
        float* Mb = g_M[it & 1];

        // ---- step 1 partial: max over b-quarter of B[a][b]*X[b] ----
        {
            const float4* Bq = (const float4*)&Bs[a*BP + 20*h];
            const float4* Xq = (const float4*)&Xs[20*h];
            float m = 0.f;
            #pragma unroll
            for (int k = 0; k < 5; ++k) {
                float4 b4 = Bq[k], x4 = Xq[k];
                m = fmaxf(m, b4.x*x4.x); m = fmaxf(m, b4.y*x4.y);
                m = fmaxf(m, b4.z*x4.z); m = fmaxf(m, b4.w*x4.w);
            }
            p1[a*4 + h] = m;
        }
        __syncthreads();
        if (t < Nn) {
            float4 pv = *(float4*)&p1[t*4];
            Mb[t*Nn + c] = fmaxf(fmaxf(pv.x, pv.y), fmaxf(pv.z, pv.w));
        }
        __syncthreads();

        // ---- publish arrival + single-word poll ----
        if (t == 0) {
            red_rel_add_u32(&g_cnt[it], 1u);
            while (ld_acq_u32(&g_cnt[it]) < (unsigned)NB) { }
        }
        __syncthreads();

        // ---- step 2 partial: sum over j-quarter of A[j]*M[a][j]; track max|M| ----
        float vmax = 0.f;
        {
            const float* base = &Mb[a*Nn + 20*h];
            float4 v0, v1, v2, v3, v4;
            ld_cg_v4(base,      v0);
            ld_cg_v4(base + 4,  v1);
            ld_cg_v4(base + 8,  v2);
            ld_cg_v4(base + 12, v3);
            ld_cg_v4(base + 16, v4);
            const float4* Aq = (const float4*)&As[20*h];
            float4 a0 = Aq[0], a1 = Aq[1], a2 = Aq[2], a3 = Aq[3], a4 = Aq[4];
            float s0 = a0.x*v0.x + a0.y*v0.y + a0.z*v0.z + a0.w*v0.w;
            float s1 = a1.x*v1.x + a1.y*v1.y + a1.z*v1.z + a1.w*v1.w;
            float s2 = a2.x*v2.x + a2.y*v2.y + a2.z*v2.z + a2.w*v2.w;
            float s3 = a3.x*v3.x + a3.y*v3.y + a3.z*v3.z + a3.w*v3.w;
            float s4 = a4.x*v4.x + a4.y*v4.y + a4.z*v4.z + a4.w*v4.w;
            p1[a*4 + h] = (s0 + s1) + (s2 + s3) + s4;
            // global max over M (all 320 threads cover all 6400 entries; M > 0)
            vmax = fmaxf(fmaxf(fmaxf(v0.x, v0.y), fmaxf(v0.z, v0.w)),
                   fmaxf(fmaxf(fmaxf(v1.x, v1.y), fmaxf(v1.z, v1.w)),
                   fmaxf(fmaxf(fmaxf(v2.x, v2.y), fmaxf(v2.z, v2.w)),
                   fmaxf(fmaxf(fmaxf(v3.x, v3.y), fmaxf(v3.z, v3.w)),
                         fmaxf(fmaxf(v4.x, v4.y), fmaxf(v4.z, v4.w))))));
        }
        #pragma unroll
        for (int o2 = 16; o2; o2 >>= 1) vmax = fmaxf(vmax, __shfl_xor_sync(0xffffffffu, vmax, o2));
        if ((t & 31) == 0) wmax[t >> 5] = vmax;
        __syncthreads();

        // ---- combine + deterministic pow2 scale (identical in every CTA) ----
        if (t < Nn) {
            float gm = wmax[0];
            #pragma unroll
            for (int w = 1; w < NT/32; ++w) gm = fmaxf(gm, wmax[w]);
            unsigned mb = __float_as_uint(gm);
            float scale = __uint_as_float((254u - ((mb >> 23) & 255u)) << 23);
            float4 pv = *(float4*)&p1[t*4];
            float xn = scale * ((pv.x + pv.y + pv.z + pv.w) + nss[t] * Xs[t]);
            Xs[t] = xn;
        }
        __syncthreads();
    }

    // ---------------- final global L2 norm (deterministic) -----------
    if (t < Nn) p1[t] = Xs[t] * Xs[t];
    __syncthreads();
    if (t == 0) {
        float ss2 = 0.f;
        #pragma unroll 16
        for (int k = 0; k < Nn; ++k) ss2 += p1[k];
        st_rel_f(&g_nrm[c], ss2);
    }
    if (t < 32) {
        bool ok;
        do {
            float v0 = ld_acq_f(&g_nrm[t]);
            float v1 = ld_acq_f(&g_nrm[t + 32]);
            float v2 = (t < 16) ? ld_acq_f(&g_nrm[t + 64]) : 1.f;
            ok = (v0 != 0.f) && (v1 != 0.f) && (v2 != 0.f);
        } while (__ballot_sync(0xffffffffu, ok) != 0xffffffffu);
    }
    __syncthreads();
    if (t == 0) {
        float tot = 0.f;
        #pragma unroll 16
        for (int k = 0; k < Nn; ++k) tot += __ldcg(&g_nrm[k]);   // fixed order everywhere
        sgv[0] = 1.f / sqrtf(tot);
    }
    __syncthreads();
    if (t < Nn) out[c*Nn + t] = Xs[t] * sgv[0];
}

// ---------------- launch ----------------
extern "C" void kernel_launch(void* const* d_in, const int* in_sizes, int n_in,
                              void* d_out, int out_size) {
    const float* x   = (const float*)d_in[0];
    const int*   ei  = (const int*)  d_in[1];
    const int*   adj = (const int*)  d_in[2];
    const float* eps = (const float*)d_in[3];
    const float* W1  = (const float*)d_in[4];
    const float* b1  = (const float*)d_in[5];
    const float* g1  = (const float*)d_in[6];
    const float* bt1 = (const float*)d_in[7];
    const float* W2  = (const float*)d_in[8];
    const float* b2  = (const float*)d_in[9];
    const float* g2  = (const float*)d_in[10];
    const float* bt2 = (const float*)d_in[11];
    const float* Wmu = (const float*)d_in[12];
    const float* bmu = (const float*)d_in[13];
    const float* Wlv = (const float*)d_in[14];
    const float* blv = (const float*)d_in[15];
    const float* We1 = (const float*)d_in[16];
    const float* be1 = (const float*)d_in[17];
    const float* We2 = (const float*)d_in[18];
    const float* be2 = (const float*)d_in[19];
    // d_in[20..23] (Wn*, bn*) are dead: B's diagonal is overwritten with 1.

    k_init<<<16, 256>>>();
    k_main<<<NB, NT>>>(x, ei, adj, eps, W1, b1, g1, bt1, W2, b2, g2, bt2,
                       Wmu, bmu, Wlv, blv, We1, be1, We2, be2, (float*)d_out);
}